// round 1
// baseline (speedup 1.0000x reference)
#include <cuda_runtime.h>
#include <math.h>

// Problem constants
constexpr int cB  = 16;
constexpr int cH  = 8;
constexpr int cNL = 256;
constexpr int cNP = 2048;
constexpr int cD  = 64;          // HID
constexpr int cNT = cNL + cNP;   // 2304

// ---------------- scratch (device globals; no runtime allocation) ----------------
__device__ float g_L1[cB * cH * cNL * cD];          // 8 MB
__device__ float g_L2[cB * cH * cNL * cD];          // 8 MB
__device__ float g_P1[cB * cH * cNP * cD];          // 64 MB
__device__ float g_P2[cB * cH * cNP * cD];          // 64 MB
__device__ float g_att[cB * cH * cNL * cNP];        // 256 MB (logits -> att in place)
__device__ float g_l3h[cB * cNL * cH * cD];         // 8 MB   [B, Nl, 512]
__device__ float g_p3h[cB * cNP * cH * cD];         // 64 MB  [B, Np, 512]
__device__ float g_y1l[cB * cNL * cD];              // 1 MB
__device__ float g_y1p[cB * cNP * cD];              // 8 MB

// =====================================================================
// Projection: out[b,h,n,d] = relu( x[b,n,:] @ w[:, h*64+d] + bias[h*64+d] )
// x: [B,N,64], w: [64,512]. Block = 64 rows x 64 cols (one head), K=64 one shot.
// =====================================================================
__global__ __launch_bounds__(256) void proj_kernel(const float* __restrict__ x,
                                                   const float* __restrict__ w,
                                                   const float* __restrict__ bias,
                                                   int N, int which) {
    float* out = (which == 0) ? g_L1 : (which == 1) ? g_L2 : (which == 2) ? g_P1 : g_P2;
    __shared__ float As[64][68];   // [k][row]
    __shared__ float Bs[64][68];   // [k][col]
    const int row0 = blockIdx.x * 64;
    const int h = blockIdx.y;
    const int tid = threadIdx.x;

    for (int i = tid; i < 64 * 64; i += 256) {
        int r = i >> 6, k = i & 63;
        As[k][r] = x[(size_t)(row0 + r) * 64 + k];
    }
    for (int i = tid; i < 64 * 64; i += 256) {
        int k = i >> 6, c = i & 63;
        Bs[k][c] = w[(size_t)k * 512 + h * 64 + c];
    }
    __syncthreads();

    const int ty = tid >> 4, tx = tid & 15;
    float acc[4][4] = {};
#pragma unroll
    for (int k = 0; k < 64; k++) {
        float4 a4 = *(const float4*)&As[k][ty * 4];
        float4 b4 = *(const float4*)&Bs[k][tx * 4];
        float a[4] = {a4.x, a4.y, a4.z, a4.w};
        float bb[4] = {b4.x, b4.y, b4.z, b4.w};
#pragma unroll
        for (int i = 0; i < 4; i++)
#pragma unroll
            for (int j = 0; j < 4; j++) acc[i][j] = fmaf(a[i], bb[j], acc[i][j]);
    }

#pragma unroll
    for (int i = 0; i < 4; i++) {
        int row = row0 + ty * 4 + i;
        int b = row / N, n = row % N;
        float4 o;
        float* op = (float*)&o;
#pragma unroll
        for (int j = 0; j < 4; j++)
            op[j] = fmaxf(acc[i][j] + bias[h * 64 + tx * 4 + j], 0.0f);
        *(float4*)&out[(((size_t)b * cH + h) * N + n) * 64 + tx * 4] = o;
    }
}

// =====================================================================
// Energy + fused distance-band mask:
//   S[b,h,l,p] = (L1[b,h,l,:]·P1[b,h,p,:] / 8) * band_h(dist[b,l,p])
// Block = 64(l) x 64(p), K=64 one shot. Mask computed inline; no inter tensor.
// =====================================================================
__global__ __launch_bounds__(256) void energy_kernel(const float* __restrict__ dist) {
    __shared__ float As[64][68];   // [k][l]
    __shared__ float Bs[64][68];   // [k][p]
    const int bh = blockIdx.z;
    const int b = bh >> 3, h = bh & 7;
    const int l0 = blockIdx.y * 64;
    const int p0 = blockIdx.x * 64;
    const float* A = g_L1 + ((size_t)bh * cNL + l0) * cD;
    const float* Bm = g_P1 + ((size_t)bh * cNP + p0) * cD;
    const int tid = threadIdx.x;

    for (int i = tid; i < 64 * 64; i += 256) {
        int r = i >> 6, k = i & 63;
        As[k][r] = A[r * 64 + k];
        Bs[k][r] = Bm[r * 64 + k];
    }
    __syncthreads();

    const int ty = tid >> 4, tx = tid & 15;
    float acc[4][4] = {};
#pragma unroll
    for (int k = 0; k < 64; k++) {
        float4 a4 = *(const float4*)&As[k][ty * 4];
        float4 b4 = *(const float4*)&Bs[k][tx * 4];
        float a[4] = {a4.x, a4.y, a4.z, a4.w};
        float bb[4] = {b4.x, b4.y, b4.z, b4.w};
#pragma unroll
        for (int i = 0; i < 4; i++)
#pragma unroll
            for (int j = 0; j < 4; j++) acc[i][j] = fmaf(a[i], bb[j], acc[i][j]);
    }

    const float hf = (float)h;
#pragma unroll
    for (int i = 0; i < 4; i++) {
        int l = l0 + ty * 4 + i;
        const float4 dv = *(const float4*)&dist[((size_t)b * cNL + l) * cNP + p0 + tx * 4];
        float dd[4] = {dv.x, dv.y, dv.z, dv.w};
        float4 o;
        float* op = (float*)&o;
#pragma unroll
        for (int j = 0; j < 4; j++) {
            float d = dd[j];
            bool m = (h < 7) ? (d > hf && d <= hf + 3.0f) : (d > 7.0f);
            float inter = m ? __fdividef(1.0f, d) : 0.0f;
            op[j] = acc[i][j] * 0.125f * inter;
        }
        *(float4*)&g_att[((size_t)bh * cNL + l) * cNP + p0 + tx * 4] = o;
    }
}

// =====================================================================
// Row softmax over p (2048), in place. One block per (b,h,l) row.
// Masked entries carry logit 0 (matching reference: softmax(energy*inter)).
// =====================================================================
__global__ __launch_bounds__(256) void softmax_kernel() {
    const size_t row = blockIdx.x;
    float4* p = (float4*)(g_att + row * (size_t)cNP);
    const int tid = threadIdx.x;
    float4 v0 = p[tid];
    float4 v1 = p[tid + 256];

    float m = fmaxf(fmaxf(fmaxf(v0.x, v0.y), fmaxf(v0.z, v0.w)),
                    fmaxf(fmaxf(v1.x, v1.y), fmaxf(v1.z, v1.w)));
    __shared__ float red[8];
#pragma unroll
    for (int o = 16; o; o >>= 1) m = fmaxf(m, __shfl_xor_sync(0xffffffffu, m, o));
    if ((tid & 31) == 0) red[tid >> 5] = m;
    __syncthreads();
    m = fmaxf(fmaxf(fmaxf(red[0], red[1]), fmaxf(red[2], red[3])),
              fmaxf(fmaxf(red[4], red[5]), fmaxf(red[6], red[7])));

    v0.x = expf(v0.x - m); v0.y = expf(v0.y - m); v0.z = expf(v0.z - m); v0.w = expf(v0.w - m);
    v1.x = expf(v1.x - m); v1.y = expf(v1.y - m); v1.z = expf(v1.z - m); v1.w = expf(v1.w - m);
    float s = v0.x + v0.y + v0.z + v0.w + v1.x + v1.y + v1.z + v1.w;
#pragma unroll
    for (int o = 16; o; o >>= 1) s += __shfl_xor_sync(0xffffffffu, s, o);
    __syncthreads();
    if ((tid & 31) == 0) red[tid >> 5] = s;
    __syncthreads();
    s = red[0] + red[1] + red[2] + red[3] + red[4] + red[5] + red[6] + red[7];

    const float inv = 1.0f / s;
    v0.x *= inv; v0.y *= inv; v0.z *= inv; v0.w *= inv;
    v1.x *= inv; v1.y *= inv; v1.z *= inv; v1.w *= inv;
    p[tid] = v0;
    p[tid + 256] = v1;
}

// =====================================================================
// l3h[b, l, h*64+d] = sum_p att[b,h,l,p] * P2[b,h,p,d]
// Block = 64(l) x 64(d), K = Np in chunks of 32.
// =====================================================================
__global__ __launch_bounds__(256) void av_kernel() {
    __shared__ float As[32][68];   // [k][l]
    __shared__ float Bs[32][68];   // [k][d]
    const int bh = blockIdx.z, b = bh >> 3, h = bh & 7;
    const int l0 = blockIdx.y * 64;
    const float* Arow = g_att + ((size_t)bh * cNL + l0) * cNP;
    const float* Bp = g_P2 + (size_t)bh * cNP * cD;
    const int tid = threadIdx.x, ty = tid >> 4, tx = tid & 15;
    float acc[4][4] = {};

    for (int k0 = 0; k0 < cNP; k0 += 32) {
        for (int i = tid; i < 64 * 32; i += 256) {
            int r = i >> 5, k = i & 31;
            As[k][r] = Arow[(size_t)r * cNP + k0 + k];
        }
        for (int i = tid; i < 32 * 64; i += 256) {
            int k = i >> 6, c = i & 63;
            Bs[k][c] = Bp[(size_t)(k0 + k) * cD + c];
        }
        __syncthreads();
#pragma unroll
        for (int k = 0; k < 32; k++) {
            float4 a4 = *(const float4*)&As[k][ty * 4];
            float4 b4 = *(const float4*)&Bs[k][tx * 4];
            float a[4] = {a4.x, a4.y, a4.z, a4.w};
            float bb[4] = {b4.x, b4.y, b4.z, b4.w};
#pragma unroll
            for (int i = 0; i < 4; i++)
#pragma unroll
                for (int j = 0; j < 4; j++) acc[i][j] = fmaf(a[i], bb[j], acc[i][j]);
        }
        __syncthreads();
    }

#pragma unroll
    for (int i = 0; i < 4; i++) {
        int l = l0 + ty * 4 + i;
        float4 o = {acc[i][0], acc[i][1], acc[i][2], acc[i][3]};
        *(float4*)&g_l3h[((size_t)b * cNL + l) * 512 + h * 64 + tx * 4] = o;
    }
}

// =====================================================================
// p3h[b, p, h*64+d] = sum_l att[b,h,l,p] * L2[b,h,l,d]
// Block = 64(p) x 64(d), K = Nl in chunks of 32. Both loads are natural-layout.
// =====================================================================
__global__ __launch_bounds__(256) void atv_kernel() {
    __shared__ float As[32][68];   // [l][p]
    __shared__ float Bs[32][68];   // [l][d]
    const int bh = blockIdx.z, b = bh >> 3, h = bh & 7;
    const int p0 = blockIdx.x * 64;
    const float* attb = g_att + (size_t)bh * cNL * cNP;
    const float* L2b = g_L2 + (size_t)bh * cNL * cD;
    const int tid = threadIdx.x, ty = tid >> 4, tx = tid & 15;
    float acc[4][4] = {};

    for (int k0 = 0; k0 < cNL; k0 += 32) {
        for (int i = tid; i < 32 * 64; i += 256) {
            int k = i >> 6, c = i & 63;
            As[k][c] = attb[(size_t)(k0 + k) * cNP + p0 + c];
            Bs[k][c] = L2b[(size_t)(k0 + k) * cD + c];
        }
        __syncthreads();
#pragma unroll
        for (int k = 0; k < 32; k++) {
            float4 a4 = *(const float4*)&As[k][ty * 4];
            float4 b4 = *(const float4*)&Bs[k][tx * 4];
            float a[4] = {a4.x, a4.y, a4.z, a4.w};
            float bb[4] = {b4.x, b4.y, b4.z, b4.w};
#pragma unroll
            for (int i = 0; i < 4; i++)
#pragma unroll
                for (int j = 0; j < 4; j++) acc[i][j] = fmaf(a[i], bb[j], acc[i][j]);
        }
        __syncthreads();
    }

#pragma unroll
    for (int i = 0; i < 4; i++) {
        int pp = p0 + ty * 4 + i;
        float4 o = {acc[i][0], acc[i][1], acc[i][2], acc[i][3]};
        *(float4*)&g_p3h[((size_t)b * cNP + pp) * 512 + h * 64 + tx * 4] = o;
    }
}

// =====================================================================
// fc1: Y[row, d] = X[row, :512] @ W[512,64] + bias.  which: 0=ligand, 1=protein
// =====================================================================
__global__ __launch_bounds__(256) void fc1_kernel(const float* __restrict__ w,
                                                  const float* __restrict__ bias, int which) {
    const float* X = which ? g_p3h : g_l3h;
    float* Y = which ? g_y1p : g_y1l;
    __shared__ float As[32][68];
    __shared__ float Bs[32][68];
    const int row0 = blockIdx.x * 64;
    const int tid = threadIdx.x, ty = tid >> 4, tx = tid & 15;
    float acc[4][4] = {};

    for (int k0 = 0; k0 < 512; k0 += 32) {
        for (int i = tid; i < 64 * 32; i += 256) {
            int r = i >> 5, k = i & 31;
            As[k][r] = X[(size_t)(row0 + r) * 512 + k0 + k];
        }
        for (int i = tid; i < 32 * 64; i += 256) {
            int k = i >> 6, c = i & 63;
            Bs[k][c] = w[(size_t)(k0 + k) * 64 + c];
        }
        __syncthreads();
#pragma unroll
        for (int k = 0; k < 32; k++) {
            float4 a4 = *(const float4*)&As[k][ty * 4];
            float4 b4 = *(const float4*)&Bs[k][tx * 4];
            float a[4] = {a4.x, a4.y, a4.z, a4.w};
            float bb[4] = {b4.x, b4.y, b4.z, b4.w};
#pragma unroll
            for (int i = 0; i < 4; i++)
#pragma unroll
                for (int j = 0; j < 4; j++) acc[i][j] = fmaf(a[i], bb[j], acc[i][j]);
        }
        __syncthreads();
    }

#pragma unroll
    for (int i = 0; i < 4; i++) {
        int row = row0 + ty * 4 + i;
        float4 o;
        float* op = (float*)&o;
#pragma unroll
        for (int j = 0; j < 4; j++) op[j] = acc[i][j] + bias[tx * 4 + j];
        *(float4*)&Y[(size_t)row * 64 + tx * 4] = o;
    }
}

// =====================================================================
// fc2 (fused concat): out = relu( [Y1, orig] @ W[128,64] + bias ), written into
// the final output at row offset row_off.
// =====================================================================
__global__ __launch_bounds__(256) void fc2_kernel(const float* __restrict__ orig,
                                                  const float* __restrict__ w,
                                                  const float* __restrict__ bias,
                                                  float* __restrict__ out,
                                                  int N, int which, int row_off) {
    const float* Y1 = which ? g_y1p : g_y1l;
    __shared__ float As[32][68];
    __shared__ float Bs[32][68];
    const int row0 = blockIdx.x * 64;
    const int tid = threadIdx.x, ty = tid >> 4, tx = tid & 15;
    float acc[4][4] = {};

    for (int k0 = 0; k0 < 128; k0 += 32) {
        const float* src = (k0 < 64) ? Y1 : orig;
        const int kb = k0 & 63;
        for (int i = tid; i < 64 * 32; i += 256) {
            int r = i >> 5, k = i & 31;
            As[k][r] = src[(size_t)(row0 + r) * 64 + kb + k];
        }
        for (int i = tid; i < 32 * 64; i += 256) {
            int k = i >> 6, c = i & 63;
            Bs[k][c] = w[(size_t)(k0 + k) * 64 + c];
        }
        __syncthreads();
#pragma unroll
        for (int k = 0; k < 32; k++) {
            float4 a4 = *(const float4*)&As[k][ty * 4];
            float4 b4 = *(const float4*)&Bs[k][tx * 4];
            float a[4] = {a4.x, a4.y, a4.z, a4.w};
            float bb[4] = {b4.x, b4.y, b4.z, b4.w};
#pragma unroll
            for (int i = 0; i < 4; i++)
#pragma unroll
                for (int j = 0; j < 4; j++) acc[i][j] = fmaf(a[i], bb[j], acc[i][j]);
        }
        __syncthreads();
    }

#pragma unroll
    for (int i = 0; i < 4; i++) {
        int row = row0 + ty * 4 + i;
        int b = row / N, n = row % N;
        float4 o;
        float* op = (float*)&o;
#pragma unroll
        for (int j = 0; j < 4; j++)
            op[j] = fmaxf(acc[i][j] + bias[tx * 4 + j], 0.0f);
        *(float4*)&out[((size_t)b * cNT + row_off + n) * 64 + tx * 4] = o;
    }
}

// =====================================================================
extern "C" void kernel_launch(void* const* d_in, const int* in_sizes, int n_in,
                              void* d_out, int out_size) {
    (void)in_sizes; (void)n_in; (void)out_size;
    const float* ligand = (const float*)d_in[0];
    const float* prot   = (const float*)d_in[1];
    const float* dist   = (const float*)d_in[2];
    const float* w_l1 = (const float*)d_in[3];
    const float* b_l1 = (const float*)d_in[4];
    const float* w_l2 = (const float*)d_in[5];
    const float* b_l2 = (const float*)d_in[6];
    const float* w_p1 = (const float*)d_in[7];
    const float* b_p1 = (const float*)d_in[8];
    const float* w_p2 = (const float*)d_in[9];
    const float* b_p2 = (const float*)d_in[10];
    const float* fc11_w = (const float*)d_in[11];
    const float* fc11_b = (const float*)d_in[12];
    const float* fc12_w = (const float*)d_in[13];
    const float* fc12_b = (const float*)d_in[14];
    const float* fc21_w = (const float*)d_in[15];
    const float* fc21_b = (const float*)d_in[16];
    const float* fc22_w = (const float*)d_in[17];
    const float* fc22_b = (const float*)d_in[18];
    float* out = (float*)d_out;

    // Projections -> [B,H,N,64] scratch
    proj_kernel<<<dim3(cB * cNL / 64, cH), 256>>>(ligand, w_l1, b_l1, cNL, 0);
    proj_kernel<<<dim3(cB * cNL / 64, cH), 256>>>(ligand, w_l2, b_l2, cNL, 1);
    proj_kernel<<<dim3(cB * cNP / 64, cH), 256>>>(prot, w_p1, b_p1, cNP, 2);
    proj_kernel<<<dim3(cB * cNP / 64, cH), 256>>>(prot, w_p2, b_p2, cNP, 3);

    // Masked energy logits -> g_att
    energy_kernel<<<dim3(cNP / 64, cNL / 64, cB * cH), 256>>>(dist);

    // Row softmax in place
    softmax_kernel<<<cB * cH * cNL, 256>>>();

    // att @ P2 -> l3h ;  att^T @ L2 -> p3h
    av_kernel<<<dim3(1, cNL / 64, cB * cH), 256>>>();
    atv_kernel<<<dim3(cNP / 64, 1, cB * cH), 256>>>();

    // FC heads
    fc1_kernel<<<cB * cNL / 64, 256>>>(fc11_w, fc11_b, 0);
    fc1_kernel<<<cB * cNP / 64, 256>>>(fc21_w, fc21_b, 1);
    fc2_kernel<<<cB * cNL / 64, 256>>>(ligand, fc12_w, fc12_b, out, cNL, 0, 0);
    fc2_kernel<<<cB * cNP / 64, 256>>>(prot, fc22_w, fc22_b, out, cNP, 1, cNL);
}